// round 2
// baseline (speedup 1.0000x reference)
#include <cuda_runtime.h>
#include <cuda_bf16.h>

#define BB 4
#define SS 2048
#define EE 1024
#define HH 16
#define DD 64
#define PITCH 68
#define NTILES (SS / 64)

static const long long OUT_ELEMS  = (long long)BB * SS * EE;        // 8388608
static const long long ATTN_ELEMS = (long long)BB * HH * SS * SS;   // 268435456

// scratch: inverse row-sums of exp(logits), one per (b,h,query-row)
__device__ float g_inv_l[BB * HH * SS];

extern __shared__ float smem_dyn[];

// Pass 1: per (b,h,64-query tile):
//   P = exp(Q K^T * scale)   (unnormalized, written to attn buffer)
//   l = rowsum(P)            (accumulated in registers, reduced at end)
//   out = (P @ V) / l        (written normalized)
__global__ __launch_bounds__(256, 1)
void attn_pass1(const float* __restrict__ q, const float* __restrict__ k,
                const float* __restrict__ v, float* __restrict__ out,
                float* __restrict__ attn, int write_attn)
{
    // dynamic smem layout (all pitch 68 floats per row)
    float* Qt = smem_dyn;              // [64 dims][PITCH] : Qt[d][query]
    float* Kt = Qt + 64 * PITCH;       // [64 dims][PITCH] : Kt[d][key]
    float* Vs = Kt + 64 * PITCH;       // [64 keys][PITCH] : Vs[key][dim]
    float* Ps = Vs + 64 * PITCH;       // [64 q][PITCH]    : Ps[query][key]
    __shared__ float red[64][17];
    __shared__ float linv[64];

    const int b = blockIdx.z, h = blockIdx.y, qt = blockIdx.x;
    const int t  = threadIdx.x;
    const int tx = t & 15;             // 16 thread cols -> 64 key/dim cols
    const int ty = t >> 4;             // 16 thread rows -> 64 query rows
    const float scale = 1.0f / 32.0f;  // 1/sqrt(EMBED_DIM=1024)

    // ---- load + transpose Q tile into Qt[d][query] ----
    const float* qg = q + ((size_t)(b * SS + qt * 64)) * EE + h * DD;
    for (int i = t; i < 1024; i += 256) {
        int r = i >> 4, c4 = i & 15;
        float4 val = *(const float4*)(qg + (size_t)r * EE + c4 * 4);
        Qt[(c4 * 4 + 0) * PITCH + r] = val.x;
        Qt[(c4 * 4 + 1) * PITCH + r] = val.y;
        Qt[(c4 * 4 + 2) * PITCH + r] = val.z;
        Qt[(c4 * 4 + 3) * PITCH + r] = val.w;
    }

    float Oacc[4][4];
#pragma unroll
    for (int i = 0; i < 4; i++)
#pragma unroll
        for (int j = 0; j < 4; j++) Oacc[i][j] = 0.0f;
    float lpart[4] = {0.0f, 0.0f, 0.0f, 0.0f};

    const float* kg0 = k + ((size_t)b * SS) * EE + h * DD;
    const float* vg0 = v + ((size_t)b * SS) * EE + h * DD;
    float* attng = attn + ((size_t)((b * HH + h) * SS) + (size_t)qt * 64) * SS;

    for (int kt = 0; kt < NTILES; kt++) {
        // ---- load K tile (transposed) and V tile ----
        const float* kg = kg0 + (size_t)kt * 64 * EE;
        const float* vg = vg0 + (size_t)kt * 64 * EE;
        for (int i = t; i < 1024; i += 256) {
            int r = i >> 4, c4 = i & 15;
            float4 kv = *(const float4*)(kg + (size_t)r * EE + c4 * 4);
            Kt[(c4 * 4 + 0) * PITCH + r] = kv.x;
            Kt[(c4 * 4 + 1) * PITCH + r] = kv.y;
            Kt[(c4 * 4 + 2) * PITCH + r] = kv.z;
            Kt[(c4 * 4 + 3) * PITCH + r] = kv.w;
            float4 vv = *(const float4*)(vg + (size_t)r * EE + c4 * 4);
            *(float4*)&Vs[r * PITCH + c4 * 4] = vv;
        }
        __syncthreads();

        // ---- S = Q K^T (4x4 micro-tile per thread) ----
        float acc[4][4];
#pragma unroll
        for (int i = 0; i < 4; i++)
#pragma unroll
            for (int j = 0; j < 4; j++) acc[i][j] = 0.0f;

#pragma unroll 8
        for (int kk = 0; kk < 64; kk++) {
            float4 a4 = *(const float4*)&Qt[kk * PITCH + ty * 4];
            float4 b4 = *(const float4*)&Kt[kk * PITCH + tx * 4];
            float a[4] = {a4.x, a4.y, a4.z, a4.w};
            float bb[4] = {b4.x, b4.y, b4.z, b4.w};
#pragma unroll
            for (int i = 0; i < 4; i++)
#pragma unroll
                for (int j = 0; j < 4; j++) acc[i][j] += a[i] * bb[j];
        }

        // ---- P = exp(S*scale) -> smem, accumulate row sums ----
#pragma unroll
        for (int i = 0; i < 4; i++) {
            float4 p4;
            p4.x = __expf(acc[i][0] * scale);
            p4.y = __expf(acc[i][1] * scale);
            p4.z = __expf(acc[i][2] * scale);
            p4.w = __expf(acc[i][3] * scale);
            lpart[i] += (p4.x + p4.y) + (p4.z + p4.w);
            *(float4*)&Ps[(ty * 4 + i) * PITCH + tx * 4] = p4;
        }
        __syncthreads();

        // ---- O += P @ V ----
#pragma unroll 8
        for (int kk = 0; kk < 64; kk++) {
            float4 b4 = *(const float4*)&Vs[kk * PITCH + tx * 4];
            float a0 = Ps[(ty * 4 + 0) * PITCH + kk];
            float a1 = Ps[(ty * 4 + 1) * PITCH + kk];
            float a2 = Ps[(ty * 4 + 2) * PITCH + kk];
            float a3 = Ps[(ty * 4 + 3) * PITCH + kk];
            Oacc[0][0] += a0 * b4.x; Oacc[0][1] += a0 * b4.y; Oacc[0][2] += a0 * b4.z; Oacc[0][3] += a0 * b4.w;
            Oacc[1][0] += a1 * b4.x; Oacc[1][1] += a1 * b4.y; Oacc[1][2] += a1 * b4.z; Oacc[1][3] += a1 * b4.w;
            Oacc[2][0] += a2 * b4.x; Oacc[2][1] += a2 * b4.y; Oacc[2][2] += a2 * b4.z; Oacc[2][3] += a2 * b4.w;
            Oacc[3][0] += a3 * b4.x; Oacc[3][1] += a3 * b4.y; Oacc[3][2] += a3 * b4.z; Oacc[3][3] += a3 * b4.w;
        }

        // ---- store unnormalized P tile to attn buffer ----
        if (write_attn) {
            for (int i = t; i < 1024; i += 256) {
                int r = i >> 4, c4 = i & 15;
                *(float4*)(attng + (size_t)r * SS + kt * 64 + c4 * 4) =
                    *(const float4*)&Ps[r * PITCH + c4 * 4];
            }
        }
        __syncthreads();
    }

    // ---- reduce row sums across the 16 thread-columns ----
#pragma unroll
    for (int i = 0; i < 4; i++) red[ty * 4 + i][tx] = lpart[i];
    __syncthreads();
    if (t < 64) {
        float s = 0.0f;
#pragma unroll
        for (int x = 0; x < 16; x++) s += red[t][x];
        float inv = 1.0f / s;
        linv[t] = inv;
        g_inv_l[(size_t)((b * HH + h) * SS) + (size_t)qt * 64 + t] = inv;
    }
    __syncthreads();

    // ---- out = O / l ----
    float* og = out + ((size_t)(b * SS + qt * 64)) * EE + h * DD;
#pragma unroll
    for (int i = 0; i < 4; i++) {
        float inv = linv[ty * 4 + i];
        float4 o4;
        o4.x = Oacc[i][0] * inv;
        o4.y = Oacc[i][1] * inv;
        o4.z = Oacc[i][2] * inv;
        o4.w = Oacc[i][3] * inv;
        *(float4*)(og + (size_t)(ty * 4 + i) * EE + tx * 4) = o4;
    }
}

// Pass 2: attn *= 1/l  (row-wise rescale; one float4 per thread)
__global__ __launch_bounds__(256)
void attn_norm(float4* __restrict__ attn)
{
    size_t idx = (size_t)blockIdx.x * 256 + threadIdx.x;   // float4 index
    size_t row = idx >> 9;                                 // 512 float4 per 2048-wide row
    float inv = g_inv_l[row];
    float4 val = attn[idx];
    val.x *= inv; val.y *= inv; val.z *= inv; val.w *= inv;
    attn[idx] = val;
}

static const size_t SHMEM_P1 = (size_t)4 * 64 * PITCH * sizeof(float);  // 69632 B

// One-time, deterministic attribute setup (not a stream op; keeps the
// capture path to pure kernel launches).
static bool setup_once()
{
    cudaFuncSetAttribute(attn_pass1, cudaFuncAttributeMaxDynamicSharedMemorySize,
                         (int)SHMEM_P1);
    return true;
}

extern "C" void kernel_launch(void* const* d_in, const int* in_sizes, int n_in,
                              void* d_out, int out_size)
{
    static bool ready = setup_once();
    (void)ready;

    const float* q = (const float*)d_in[0];
    const float* k = (const float*)d_in[1];
    const float* v = (const float*)d_in[2];
    float* out  = (float*)d_out;
    float* attn = out + OUT_ELEMS;

    const long long need = OUT_ELEMS + ATTN_ELEMS;
    const int write_attn = ((long long)out_size >= need) ? 1 : 0;

    dim3 grid(SS / 64, HH, BB);
    attn_pass1<<<grid, 256, SHMEM_P1>>>(q, k, v, out, attn, write_attn);

    if (write_attn) {
        long long nblk = (ATTN_ELEMS / 4) / 256;  // 262144
        attn_norm<<<(unsigned)nblk, 256>>>((float4*)attn);
    }
}

// round 3
// speedup vs baseline: 2.4898x; 2.4898x over previous
#include <cuda_runtime.h>
#include <cuda_bf16.h>
#include <cstdint>

#define BB 4
#define SS 2048
#define EE 1024
#define HH 16
#define DD 64
#define NTILES 32
#define PK 68   // Kt pitch (floats): QK B-frag loads conflict-free
#define PVP 72  // Vs pitch (floats): PV B-frag loads conflict-free
#define PP 68   // Ps pitch (floats): PV A-frag loads conflict-free

static const long long OUT_ELEMS  = (long long)BB * SS * EE;        // 8388608
static const long long ATTN_ELEMS = (long long)BB * HH * SS * SS;   // 268435456

// inverse row-sums of exp(logits), one per (b,h,query-row)
__device__ float g_inv_l[BB * HH * SS];

__device__ __forceinline__ uint32_t f2tf(float x) {
    uint32_t r;
    asm("cvt.rna.tf32.f32 %0, %1;" : "=r"(r) : "f"(x));
    return r;
}

__device__ __forceinline__ void mma_tf32(float& c0, float& c1, float& c2, float& c3,
                                         uint32_t a0, uint32_t a1, uint32_t a2, uint32_t a3,
                                         uint32_t b0, uint32_t b1)
{
    asm volatile(
        "mma.sync.aligned.m16n8k8.row.col.f32.tf32.tf32.f32 "
        "{%0,%1,%2,%3}, {%4,%5,%6,%7}, {%8,%9}, {%0,%1,%2,%3};"
        : "+f"(c0), "+f"(c1), "+f"(c2), "+f"(c3)
        : "r"(a0), "r"(a1), "r"(a2), "r"(a3), "r"(b0), "r"(b1));
}

extern __shared__ float smem_dyn[];

// One CTA = (b, h, 64-query tile). 4 warps; warp w owns q-rows [w*16, w*16+16).
// Per 64-key tile: S = Q K^T (tf32 mma) -> P = exp(S*scale) -> attn (unnorm),
// O += P V (tf32 mma), l += rowsum(P). Epilogue: out = O / l, g_inv_l = 1/l.
__global__ __launch_bounds__(128, 3)
void attn_pass1(const float* __restrict__ q, const float* __restrict__ k,
                const float* __restrict__ v, float* __restrict__ out,
                float* __restrict__ attn, int write_attn)
{
    float* Kt = smem_dyn;              // [64 keys][PK dims]  (rounded tf32 values)
    float* Vs = Kt + 64 * PK;          // [64 keys][PVP dims] (rounded tf32 values)
    float* Ps = Vs + 64 * PVP;         // [64 q][PP keys]     (full fp32 exp values)

    const int b = blockIdx.z, h = blockIdx.y, qt = blockIdx.x;
    const int t    = threadIdx.x;
    const int w    = t >> 5;
    const int lane = t & 31;
    const int gid  = lane >> 2;        // 0..7
    const int tid4 = lane & 3;         // 0..3
    const float scale = 1.0f / 32.0f;  // 1/sqrt(EMBED_DIM)

    const int qr0 = w * 16 + gid;      // this thread's first q-row (local)

    // ---- Q fragments: load once from gmem, round to tf32, keep in regs ----
    const float* qg = q + ((size_t)(b * SS + qt * 64)) * EE + h * DD;
    uint32_t A[8][4];
#pragma unroll
    for (int kb = 0; kb < 8; kb++) {
        A[kb][0] = f2tf(qg[(size_t)qr0       * EE + kb * 8 + tid4]);
        A[kb][1] = f2tf(qg[(size_t)(qr0 + 8) * EE + kb * 8 + tid4]);
        A[kb][2] = f2tf(qg[(size_t)qr0       * EE + kb * 8 + tid4 + 4]);
        A[kb][3] = f2tf(qg[(size_t)(qr0 + 8) * EE + kb * 8 + tid4 + 4]);
    }

    float Oacc[8][4];
#pragma unroll
    for (int nb = 0; nb < 8; nb++)
#pragma unroll
        for (int j = 0; j < 4; j++) Oacc[nb][j] = 0.0f;
    float lp0 = 0.0f, lp1 = 0.0f;

    const float* kg0 = k + ((size_t)b * SS) * EE + h * DD;
    const float* vg0 = v + ((size_t)b * SS) * EE + h * DD;
    float* attng = attn + ((size_t)((b * HH + h) * SS) + (size_t)qt * 64) * SS;

    for (int kt = 0; kt < NTILES; kt++) {
        // ---- stage K, V tiles (rounded to tf32) ----
        const float* kg = kg0 + (size_t)kt * 64 * EE;
        const float* vg = vg0 + (size_t)kt * 64 * EE;
        for (int i = t; i < 1024; i += 128) {
            int r = i >> 4, c4 = i & 15;
            float4 kv = *(const float4*)(kg + (size_t)r * EE + c4 * 4);
            float4 ko;
            ko.x = __uint_as_float(f2tf(kv.x));
            ko.y = __uint_as_float(f2tf(kv.y));
            ko.z = __uint_as_float(f2tf(kv.z));
            ko.w = __uint_as_float(f2tf(kv.w));
            *(float4*)&Kt[r * PK + c4 * 4] = ko;
            float4 vv = *(const float4*)(vg + (size_t)r * EE + c4 * 4);
            float4 vo;
            vo.x = __uint_as_float(f2tf(vv.x));
            vo.y = __uint_as_float(f2tf(vv.y));
            vo.z = __uint_as_float(f2tf(vv.z));
            vo.w = __uint_as_float(f2tf(vv.w));
            *(float4*)&Vs[r * PVP + c4 * 4] = vo;
        }
        __syncthreads();

        // ---- S = Q K^T ----
        float S[8][4];
#pragma unroll
        for (int nb = 0; nb < 8; nb++)
#pragma unroll
            for (int j = 0; j < 4; j++) S[nb][j] = 0.0f;

#pragma unroll
        for (int kb = 0; kb < 8; kb++) {
#pragma unroll
            for (int nb = 0; nb < 8; nb++) {
                uint32_t b0 = __float_as_uint(Kt[(nb * 8 + gid) * PK + kb * 8 + tid4]);
                uint32_t b1 = __float_as_uint(Kt[(nb * 8 + gid) * PK + kb * 8 + tid4 + 4]);
                mma_tf32(S[nb][0], S[nb][1], S[nb][2], S[nb][3],
                         A[kb][0], A[kb][1], A[kb][2], A[kb][3], b0, b1);
            }
        }

        // ---- P = exp(S*scale): accumulate row sums, store fp32 to Ps ----
#pragma unroll
        for (int nb = 0; nb < 8; nb++) {
            float p0 = __expf(S[nb][0] * scale);
            float p1 = __expf(S[nb][1] * scale);
            float p2 = __expf(S[nb][2] * scale);
            float p3 = __expf(S[nb][3] * scale);
            lp0 += p0 + p1;
            lp1 += p2 + p3;
            float2 lo = make_float2(p0, p1);
            float2 hi = make_float2(p2, p3);
            *(float2*)&Ps[(size_t)qr0       * PP + nb * 8 + 2 * tid4] = lo;
            *(float2*)&Ps[(size_t)(qr0 + 8) * PP + nb * 8 + 2 * tid4] = hi;
        }
        // warp w wrote exactly rows [w*16, w*16+16) of Ps and only reads those
        // rows below -> no barrier needed before PV or the attn store.

        // ---- O += P V ----
#pragma unroll
        for (int kb = 0; kb < 8; kb++) {
            uint32_t pa0 = f2tf(Ps[(size_t)qr0       * PP + kb * 8 + tid4]);
            uint32_t pa1 = f2tf(Ps[(size_t)(qr0 + 8) * PP + kb * 8 + tid4]);
            uint32_t pa2 = f2tf(Ps[(size_t)qr0       * PP + kb * 8 + tid4 + 4]);
            uint32_t pa3 = f2tf(Ps[(size_t)(qr0 + 8) * PP + kb * 8 + tid4 + 4]);
#pragma unroll
            for (int nb = 0; nb < 8; nb++) {
                uint32_t b0 = __float_as_uint(Vs[(kb * 8 + tid4)     * PVP + nb * 8 + gid]);
                uint32_t b1 = __float_as_uint(Vs[(kb * 8 + tid4 + 4) * PVP + nb * 8 + gid]);
                mma_tf32(Oacc[nb][0], Oacc[nb][1], Oacc[nb][2], Oacc[nb][3],
                         pa0, pa1, pa2, pa3, b0, b1);
            }
        }

        // ---- store unnormalized P tile (each warp stores its own 16 rows) ----
        if (write_attn) {
            float* ag = attng + kt * 64;
            for (int i = lane; i < 256; i += 32) {
                int r = w * 16 + (i >> 4), c4 = i & 15;
                *(float4*)(ag + (size_t)r * SS + c4 * 4) = *(const float4*)&Ps[r * PP + c4 * 4];
            }
        }
        __syncthreads();   // protect Kt/Vs/Ps restage next iteration
    }

    // ---- reduce row sums within each 4-lane group (same q-rows) ----
    lp0 += __shfl_xor_sync(0xFFFFFFFFu, lp0, 1);
    lp0 += __shfl_xor_sync(0xFFFFFFFFu, lp0, 2);
    lp1 += __shfl_xor_sync(0xFFFFFFFFu, lp1, 1);
    lp1 += __shfl_xor_sync(0xFFFFFFFFu, lp1, 2);
    float inv0 = 1.0f / lp0;
    float inv1 = 1.0f / lp1;

    if (tid4 == 0) {
        size_t base = (size_t)((b * HH + h) * SS) + (size_t)qt * 64;
        g_inv_l[base + qr0]     = inv0;
        g_inv_l[base + qr0 + 8] = inv1;
    }

    // ---- out = O / l ----
    float* og = out + ((size_t)(b * SS + qt * 64)) * EE + h * DD;
#pragma unroll
    for (int nb = 0; nb < 8; nb++) {
        float2 lo = make_float2(Oacc[nb][0] * inv0, Oacc[nb][1] * inv0);
        float2 hi = make_float2(Oacc[nb][2] * inv1, Oacc[nb][3] * inv1);
        *(float2*)(og + (size_t)qr0       * EE + nb * 8 + 2 * tid4) = lo;
        *(float2*)(og + (size_t)(qr0 + 8) * EE + nb * 8 + 2 * tid4) = hi;
    }
}

// Pass 2: attn *= 1/l (row-wise rescale) — measured at 83.9% DRAM, at roofline.
__global__ __launch_bounds__(256)
void attn_norm(float4* __restrict__ attn)
{
    size_t idx = (size_t)blockIdx.x * 256 + threadIdx.x;   // float4 index
    size_t row = idx >> 9;                                 // 512 float4 per row
    float inv = g_inv_l[row];
    float4 val = attn[idx];
    val.x *= inv; val.y *= inv; val.z *= inv; val.w *= inv;
    attn[idx] = val;
}

static const size_t SHMEM_P1 = (size_t)64 * (PK + PVP + PP) * sizeof(float);  // 53248 B

static bool setup_once()
{
    cudaFuncSetAttribute(attn_pass1, cudaFuncAttributeMaxDynamicSharedMemorySize,
                         (int)SHMEM_P1);
    return true;
}

extern "C" void kernel_launch(void* const* d_in, const int* in_sizes, int n_in,
                              void* d_out, int out_size)
{
    static bool ready = setup_once();
    (void)ready;

    const float* q = (const float*)d_in[0];
    const float* k = (const float*)d_in[1];
    const float* v = (const float*)d_in[2];
    float* out  = (float*)d_out;
    float* attn = out + OUT_ELEMS;

    const long long need = OUT_ELEMS + ATTN_ELEMS;
    const int write_attn = ((long long)out_size >= need) ? 1 : 0;

    dim3 grid(SS / 64, HH, BB);
    attn_pass1<<<grid, 128, SHMEM_P1>>>(q, k, v, out, attn, write_attn);

    if (write_attn) {
        long long nblk = (ATTN_ELEMS / 4) / 256;  // 262144
        attn_norm<<<(unsigned)nblk, 256>>>((float4*)attn);
    }
}